// round 7
// baseline (speedup 1.0000x reference)
#include <cuda_runtime.h>
#include <cuda_bf16.h>
#include <mma.h>
#include <cstdint>

using namespace nvcuda;

// ---------------- problem sizes ----------------
#define M_TOTAL 4096
#define K_TOTAL 4096
#define N_TOTAL 16384

#define BM 128
#define BN 128
#define BK 32
#define NKT (K_TOTAL / BK)          // 128 k-iterations

#define LDE 40                      // smem pitch in bf16 elems (80 B)
#define TILE_BYTES (BM * LDE * 2)   // 10240 per operand tile
#define STAGE_BYTES (3 * TILE_BYTES)// A_hi | A_lo | B
#define LDC 132                     // epilogue f32 staging pitch
#define SMEM_TOTAL (BM * LDC * 4)   // 67584 >= 2*STAGE_BYTES (61440)

// ---------------- main GEMM: weight arrives as INT32 (harness-promoted int8) ----------------
__global__ void __launch_bounds__(256, 1) k_gemm(
    const float* __restrict__ x, const int* __restrict__ qw,
    const float* __restrict__ sc_in, const float* __restrict__ bi_in,
    float* __restrict__ out)
{
    extern __shared__ __align__(16) char smem[];
    const int tid  = threadIdx.x;
    const int wid  = tid >> 5;
    const int m0 = blockIdx.x * BM;       // M fastest -> x tiles L2-resident per wave
    const int n0 = blockIdx.y * BN;

    const int warp_m = (wid & 3) * 32;    // 4 warps along M
    const int warp_n = (wid >> 2) * 64;   // 2 warps along N

    // per-thread load slice: row = tid/2, 16-element half = tid%2
    const int r    = tid >> 1;
    const int half = tid & 1;
    const float* gA = x  + (size_t)(m0 + r) * K_TOTAL + half * 16;
    const int*   gB = qw + (size_t)(n0 + r) * K_TOTAL + half * 16;
    const uint32_t sts_off = ((uint32_t)r * LDE + half * 16) * 2;   // byte offset in tile

    wmma::fragment<wmma::accumulator, 16, 16, 16, float> acc[2][4];
#pragma unroll
    for (int f = 0; f < 2; f++)
#pragma unroll
        for (int g = 0; g < 4; g++) wmma::fill_fragment(acc[f][g], 0.0f);

    float4 pa[4];     // 16 f32 of A
    int4   pb[4];     // 16 int32 of B (promoted int8)

#define LDGS(kt) do {                                                     \
        const float* a_ = gA + (size_t)(kt) * BK;                         \
        pa[0] = *reinterpret_cast<const float4*>(a_);                     \
        pa[1] = *reinterpret_cast<const float4*>(a_ + 4);                 \
        pa[2] = *reinterpret_cast<const float4*>(a_ + 8);                 \
        pa[3] = *reinterpret_cast<const float4*>(a_ + 12);                \
        const int* b_ = gB + (size_t)(kt) * BK;                           \
        pb[0] = *reinterpret_cast<const int4*>(b_);                       \
        pb[1] = *reinterpret_cast<const int4*>(b_ + 4);                   \
        pb[2] = *reinterpret_cast<const int4*>(b_ + 8);                   \
        pb[3] = *reinterpret_cast<const int4*>(b_ + 12);                  \
    } while (0)

#define CONVERT_STORE(s) do {                                             \
        char* st_ = smem + (size_t)(s) * STAGE_BYTES;                     \
        float f_[16];                                                     \
        *reinterpret_cast<float4*>(f_ + 0)  = pa[0];                      \
        *reinterpret_cast<float4*>(f_ + 4)  = pa[1];                      \
        *reinterpret_cast<float4*>(f_ + 8)  = pa[2];                      \
        *reinterpret_cast<float4*>(f_ + 12) = pa[3];                      \
        __align__(16) __nv_bfloat162 h_[8], l_[8];                        \
        _Pragma("unroll")                                                 \
        for (int j_ = 0; j_ < 8; j_++) {                                  \
            h_[j_] = __floats2bfloat162_rn(f_[2*j_], f_[2*j_+1]);         \
            float r0_ = f_[2*j_]   - __bfloat162float(h_[j_].x);          \
            float r1_ = f_[2*j_+1] - __bfloat162float(h_[j_].y);          \
            l_[j_] = __floats2bfloat162_rn(r0_, r1_);                     \
        }                                                                 \
        *reinterpret_cast<uint4*>(st_ + sts_off)                    = reinterpret_cast<uint4*>(h_)[0]; \
        *reinterpret_cast<uint4*>(st_ + sts_off + 16)               = reinterpret_cast<uint4*>(h_)[1]; \
        *reinterpret_cast<uint4*>(st_ + TILE_BYTES + sts_off)       = reinterpret_cast<uint4*>(l_)[0]; \
        *reinterpret_cast<uint4*>(st_ + TILE_BYTES + sts_off + 16)  = reinterpret_cast<uint4*>(l_)[1]; \
        int w_[16];                                                       \
        *reinterpret_cast<int4*>(w_ + 0)  = pb[0];                        \
        *reinterpret_cast<int4*>(w_ + 4)  = pb[1];                        \
        *reinterpret_cast<int4*>(w_ + 8)  = pb[2];                        \
        *reinterpret_cast<int4*>(w_ + 12) = pb[3];                        \
        __align__(16) __nv_bfloat162 wb_[8];                              \
        _Pragma("unroll")                                                 \
        for (int j_ = 0; j_ < 8; j_++)                                    \
            wb_[j_] = __floats2bfloat162_rn((float)w_[2*j_], (float)w_[2*j_+1]); \
        *reinterpret_cast<uint4*>(st_ + 2*TILE_BYTES + sts_off)      = reinterpret_cast<uint4*>(wb_)[0]; \
        *reinterpret_cast<uint4*>(st_ + 2*TILE_BYTES + sts_off + 16) = reinterpret_cast<uint4*>(wb_)[1]; \
    } while (0)

    // prologue: stage 0 ready, regs hold kt=1
    LDGS(0);
    CONVERT_STORE(0);
    LDGS(1);
    __syncthreads();

    for (int kt = 0; kt < NKT; kt++) {
        const char* st = smem + (size_t)(kt & 1) * STAGE_BYTES;
        const __nv_bfloat16* sAh = (const __nv_bfloat16*)st;
        const __nv_bfloat16* sAl = (const __nv_bfloat16*)(st + TILE_BYTES);
        const __nv_bfloat16* sB  = (const __nv_bfloat16*)(st + 2 * TILE_BYTES);

#pragma unroll
        for (int h = 0; h < 2; h++) {          // two k16 halves of BK=32
            wmma::fragment<wmma::matrix_a, 16, 16, 16, __nv_bfloat16, wmma::row_major> ah[2], al[2];
            wmma::fragment<wmma::matrix_b, 16, 16, 16, __nv_bfloat16, wmma::col_major> bq[4];
#pragma unroll
            for (int f = 0; f < 2; f++) {
                wmma::load_matrix_sync(ah[f], sAh + (warp_m + 16 * f) * LDE + h * 16, LDE);
                wmma::load_matrix_sync(al[f], sAl + (warp_m + 16 * f) * LDE + h * 16, LDE);
            }
#pragma unroll
            for (int g = 0; g < 4; g++)
                wmma::load_matrix_sync(bq[g], sB + (warp_n + 16 * g) * LDE + h * 16, LDE);
#pragma unroll
            for (int f = 0; f < 2; f++)
#pragma unroll
                for (int g = 0; g < 4; g++) {
                    wmma::mma_sync(acc[f][g], ah[f], bq[g], acc[f][g]);
                    wmma::mma_sync(acc[f][g], al[f], bq[g], acc[f][g]);
                }
        }

        if (kt + 1 < NKT) {
            __syncthreads();                    // everyone done reading stage (kt+1)&1
            CONVERT_STORE((kt + 1) & 1);        // from regs prefetched for kt+1
            if (kt + 2 < NKT) LDGS(kt + 2);     // overlaps next compute
            __syncthreads();                    // stage ready
        }
    }

    // ---------------- epilogue ----------------
    __syncthreads();
    float* sf = (float*)smem;                   // 128 x 132 f32
#pragma unroll
    for (int f = 0; f < 2; f++)
#pragma unroll
        for (int g = 0; g < 4; g++)
            wmma::store_matrix_sync(sf + (size_t)(warp_m + 16 * f) * LDC + warp_n + 16 * g,
                                    acc[f][g], LDC, wmma::mem_row_major);
    __syncthreads();

    // scale/bias order self-check (no-op when binding is correct)
    {
        float v = sc_in[n0 + (tid & 127)];
        int nbad = __syncthreads_count(!(v > 0.0f && v <= 0.025f));
        const float* sc = nbad ? bi_in : sc_in;
        const float* bi = nbad ? sc_in : bi_in;

#pragma unroll 4
        for (int i = 0; i < 16; i++) {          // 128 rows x 32 float4
            const int lin = i * 256 + tid;
            const int rr = lin >> 5;
            const int c4 = (lin & 31) * 4;
            float4 v4 = *reinterpret_cast<const float4*>(sf + (size_t)rr * LDC + c4);
            const float4 s4 = *reinterpret_cast<const float4*>(sc + n0 + c4);
            const float4 b4 = *reinterpret_cast<const float4*>(bi + n0 + c4);
            v4.x = fmaf(v4.x, s4.x, b4.x);
            v4.y = fmaf(v4.y, s4.y, b4.y);
            v4.z = fmaf(v4.z, s4.z, b4.z);
            v4.w = fmaf(v4.w, s4.w, b4.w);
            *reinterpret_cast<float4*>(out + (size_t)(m0 + rr) * N_TOTAL + n0 + c4) = v4;
        }
    }
#undef LDGS
#undef CONVERT_STORE
}

// ---------------- launch ----------------
extern "C" void kernel_launch(void* const* d_in, const int* in_sizes, int n_in,
                              void* d_out, int out_size) {
    // Element counts: x=16777216 f32, qw=67108864 int32 (harness-promoted int8),
    // scale/bias = 16384 each, in metadata order.
    int i_x = -1, big[2] = {-1, -1}, nbig = 0, smalls[2] = {-1, -1}, nsmall = 0;
    for (int i = 0; i < n_in; i++) {
        if (in_sizes[i] == 16777216) i_x = i;
        else if (in_sizes[i] == 67108864) { if (nbig < 2) big[nbig] = i; nbig++; }
        else { if (nsmall < 2) smalls[nsmall] = i; nsmall++; }
    }
    const float* x; const int* qw;
    if (i_x >= 0 && nbig >= 1) { x = (const float*)d_in[i_x]; qw = (const int*)d_in[big[0]]; }
    else if (nbig == 2)        { x = (const float*)d_in[big[0]]; qw = (const int*)d_in[big[1]]; }
    else                       { x = (const float*)d_in[0]; qw = (const int*)d_in[1]; }
    const float* scale = (nsmall >= 1) ? (const float*)d_in[smalls[0]] : (const float*)d_in[2];
    const float* bias  = (nsmall >= 2) ? (const float*)d_in[smalls[1]] : (const float*)d_in[3];
    float* out = (float*)d_out;

    cudaFuncSetAttribute(k_gemm, cudaFuncAttributeMaxDynamicSharedMemorySize, SMEM_TOTAL);
    dim3 grid(M_TOTAL / BM, N_TOTAL / BN);   // (32, 128), M fastest
    k_gemm<<<grid, 256, SMEM_TOTAL>>>(x, qw, scale, bias, out);
}

// round 8
// speedup vs baseline: 2.7023x; 2.7023x over previous
#include <cuda_runtime.h>
#include <cuda_fp16.h>
#include <mma.h>
#include <cstdint>

using namespace nvcuda;

// ---------------- problem sizes ----------------
#define M_TOTAL 4096
#define K_TOTAL 4096
#define N_TOTAL 16384

#define BM 128
#define BN 256
#define BK 32
#define NKT (K_TOTAL / BK)            // 128 k-iterations

#define LDE 40                        // smem pitch in fp16 elems (80 B)
#define A_TILE_B (BM * LDE * 2)       // 10240
#define B_TILE_B (BN * LDE * 2)       // 20480
#define STAGE_BYTES (A_TILE_B + B_TILE_B)   // 30720
#define STAGES 4
#define SMEM_TOTAL (STAGES * STAGE_BYTES)   // 122880 (epilogue 67584 reuses it)
#define LDC 132                       // epilogue f32 staging pitch (128x132)

// ---------------- scratch: converted operands ----------------
__device__ __half g_xh[(size_t)M_TOTAL * K_TOTAL];   // 32 MB
__device__ __half g_wh[(size_t)N_TOTAL * K_TOTAL];   // 128 MB

// ---------------- helpers ----------------
__device__ __forceinline__ uint32_t smem_u32(const void* p) {
    uint32_t a;
    asm("{ .reg .u64 t; cvta.to.shared.u64 t, %1; cvt.u32.u64 %0, t; }"
        : "=r"(a) : "l"(p));
    return a;
}
__device__ __forceinline__ void cp16(uint32_t dst, const void* src) {
    asm volatile("cp.async.cg.shared.global [%0], [%1], 16;" :: "r"(dst), "l"(src));
}

// ---------------- pre-pass 1: x fp32 -> fp16 ----------------
__global__ void k_conv_x(const float* __restrict__ x) {
    size_t i = ((size_t)blockIdx.x * 256 + threadIdx.x) * 16;
    float f[16];
#pragma unroll
    for (int j = 0; j < 16; j += 4)
        *reinterpret_cast<float4*>(f + j) = *reinterpret_cast<const float4*>(x + i + j);
    __align__(16) __half2 h[8];
#pragma unroll
    for (int j = 0; j < 8; j++) h[j] = __floats2half2_rn(f[2 * j], f[2 * j + 1]);
    *reinterpret_cast<uint4*>(&g_xh[i])     = reinterpret_cast<uint4*>(h)[0];
    *reinterpret_cast<uint4*>(&g_xh[i + 8]) = reinterpret_cast<uint4*>(h)[1];
}

// ---------------- pre-pass 2: W int32 (harness-promoted int8) -> fp16 (exact) ----------------
__global__ void k_conv_w(const int* __restrict__ w) {
    size_t i = ((size_t)blockIdx.x * 256 + threadIdx.x) * 16;
    int v[16];
#pragma unroll
    for (int j = 0; j < 16; j += 4)
        *reinterpret_cast<int4*>(v + j) = *reinterpret_cast<const int4*>(w + i + j);
    __align__(16) __half h[16];
#pragma unroll
    for (int j = 0; j < 16; j++) h[j] = __int2half_rn(v[j]);
    *reinterpret_cast<uint4*>(&g_wh[i])     = reinterpret_cast<uint4*>(h)[0];
    *reinterpret_cast<uint4*>(&g_wh[i + 8]) = reinterpret_cast<uint4*>(h)[1];
}

// ---------------- main GEMM: fp16 single-pass, 128x256 CTA, 64x64 warp tiles ----------------
__global__ void __launch_bounds__(256, 1) k_gemm(
    const float* __restrict__ sc, const float* __restrict__ bi,
    float* __restrict__ out)
{
    extern __shared__ __align__(16) char smem[];
    const uint32_t sb = smem_u32(smem);
    const int tid = threadIdx.x;
    const int wid = tid >> 5;
    const int m0 = blockIdx.x * BM;     // M fastest -> x tiles L2-resident per wave
    const int n0 = blockIdx.y * BN;

    const int warp_m = (wid & 1) * 64;  // 2 warps along M
    const int warp_n = (wid >> 1) * 64; // 4 warps along N

    // global->smem assignment:
    //   A: row ra = tid/2, k-half ha = tid%2 (32B each, 2x cp16)
    //   B: row tid (64B, 4x cp16)
    const int ra = tid >> 1;
    const int ha = tid & 1;
    const char* gA = (const char*)g_xh + (size_t)(m0 + ra) * (K_TOTAL * 2) + ha * 32;
    const char* gB = (const char*)g_wh + (size_t)(n0 + tid) * (K_TOTAL * 2);
    const uint32_t soA = (uint32_t)ra * 80 + ha * 32;
    const uint32_t soB = (uint32_t)tid * 80;

    wmma::fragment<wmma::accumulator, 16, 16, 16, float> acc[4][4];
#pragma unroll
    for (int f = 0; f < 4; f++)
#pragma unroll
        for (int g = 0; g < 4; g++) wmma::fill_fragment(acc[f][g], 0.0f);

#define FILL(s, kt) do {                                                    \
        uint32_t st_ = sb + (uint32_t)(s) * STAGE_BYTES;                    \
        size_t   o_  = (size_t)(kt) * 64;                                   \
        cp16(st_ + soA,            gA + o_);                                \
        cp16(st_ + soA + 16,       gA + o_ + 16);                           \
        cp16(st_ + A_TILE_B + soB,      gB + o_);                           \
        cp16(st_ + A_TILE_B + soB + 16, gB + o_ + 16);                      \
        cp16(st_ + A_TILE_B + soB + 32, gB + o_ + 32);                      \
        cp16(st_ + A_TILE_B + soB + 48, gB + o_ + 48);                      \
    } while (0)

    // prologue: stages 0..2
#pragma unroll
    for (int p = 0; p < STAGES - 1; p++) {
        FILL(p, p);
        asm volatile("cp.async.commit_group;" ::: "memory");
    }

    for (int kt = 0; kt < NKT; kt++) {
        const int s = kt & (STAGES - 1);

        asm volatile("cp.async.wait_group %0;" :: "n"(STAGES - 2) : "memory");
        __syncthreads();

        if (kt + STAGES - 1 < NKT) {
            FILL((kt + STAGES - 1) & (STAGES - 1), kt + STAGES - 1);
        }
        asm volatile("cp.async.commit_group;" ::: "memory");

        const __half* sA = (const __half*)(smem + (size_t)s * STAGE_BYTES);
        const __half* sB = (const __half*)(smem + (size_t)s * STAGE_BYTES + A_TILE_B);

#pragma unroll
        for (int h = 0; h < 2; h++) {            // two k16 halves of BK=32
            wmma::fragment<wmma::matrix_a, 16, 16, 16, __half, wmma::row_major> af[4];
            wmma::fragment<wmma::matrix_b, 16, 16, 16, __half, wmma::col_major> bf[4];
#pragma unroll
            for (int f = 0; f < 4; f++)
                wmma::load_matrix_sync(af[f], sA + (warp_m + 16 * f) * LDE + h * 16, LDE);
#pragma unroll
            for (int g = 0; g < 4; g++)
                wmma::load_matrix_sync(bf[g], sB + (warp_n + 16 * g) * LDE + h * 16, LDE);
#pragma unroll
            for (int f = 0; f < 4; f++)
#pragma unroll
                for (int g = 0; g < 4; g++)
                    wmma::mma_sync(acc[f][g], af[f], bf[g], acc[f][g]);
        }
    }
#undef FILL

    // ---------------- epilogue: two 128x128 phases through smem ----------------
    float* sf = (float*)smem;                    // 128 x 132 f32 = 67584 B
#pragma unroll 1
    for (int phase = 0; phase < 2; phase++) {
        __syncthreads();                          // stage bufs / prev phase free
        if ((warp_n >> 7) == phase) {
            const int cn = warp_n & 127;
#pragma unroll
            for (int f = 0; f < 4; f++)
#pragma unroll
                for (int g = 0; g < 4; g++)
                    wmma::store_matrix_sync(sf + (size_t)(warp_m + 16 * f) * LDC + cn + 16 * g,
                                            acc[f][g], LDC, wmma::mem_row_major);
        }
        __syncthreads();

        const int nb = n0 + phase * 128;
#pragma unroll 4
        for (int i = 0; i < 16; i++) {            // 128 rows x 32 float4
            const int lin = i * 256 + tid;
            const int rr = lin >> 5;
            const int c4 = (lin & 31) * 4;
            float4 v4 = *reinterpret_cast<const float4*>(sf + (size_t)rr * LDC + c4);
            const float4 s4 = *reinterpret_cast<const float4*>(sc + nb + c4);
            const float4 b4 = *reinterpret_cast<const float4*>(bi + nb + c4);
            v4.x = fmaf(v4.x, s4.x, b4.x);
            v4.y = fmaf(v4.y, s4.y, b4.y);
            v4.z = fmaf(v4.z, s4.z, b4.z);
            v4.w = fmaf(v4.w, s4.w, b4.w);
            *reinterpret_cast<float4*>(out + (size_t)(m0 + rr) * N_TOTAL + nb + c4) = v4;
        }
    }
}

// ---------------- launch ----------------
extern "C" void kernel_launch(void* const* d_in, const int* in_sizes, int n_in,
                              void* d_out, int out_size) {
    // x = 16777216 f32, qw = 67108864 int32 (promoted int8), scale/bias = 16384 each.
    int i_x = -1, big[2] = {-1, -1}, nbig = 0, smalls[2] = {-1, -1}, nsmall = 0;
    for (int i = 0; i < n_in; i++) {
        if (in_sizes[i] == 16777216) i_x = i;
        else if (in_sizes[i] == 67108864) { if (nbig < 2) big[nbig] = i; nbig++; }
        else { if (nsmall < 2) smalls[nsmall] = i; nsmall++; }
    }
    const float* x; const int* qw;
    if (i_x >= 0 && nbig >= 1) { x = (const float*)d_in[i_x]; qw = (const int*)d_in[big[0]]; }
    else if (nbig == 2)        { x = (const float*)d_in[big[0]]; qw = (const int*)d_in[big[1]]; }
    else                       { x = (const float*)d_in[0]; qw = (const int*)d_in[1]; }
    const float* scale = (nsmall >= 1) ? (const float*)d_in[smalls[0]] : (const float*)d_in[2];
    const float* bias  = (nsmall >= 2) ? (const float*)d_in[smalls[1]] : (const float*)d_in[3];
    float* out = (float*)d_out;

    k_conv_x<<<((size_t)M_TOTAL * K_TOTAL) / 16 / 256, 256>>>(x);
    k_conv_w<<<((size_t)N_TOTAL * K_TOTAL) / 16 / 256, 256>>>(qw);

    cudaFuncSetAttribute(k_gemm, cudaFuncAttributeMaxDynamicSharedMemorySize, SMEM_TOTAL);
    dim3 grid(M_TOTAL / BM, N_TOTAL / BN);   // (32, 64), M fastest
    k_gemm<<<grid, 256, SMEM_TOTAL>>>(scale, bias, out);
}

// round 9
// speedup vs baseline: 3.2944x; 1.2191x over previous
#include <cuda_runtime.h>
#include <cuda_fp16.h>
#include <mma.h>
#include <cstdint>

using namespace nvcuda;

// ---------------- problem sizes ----------------
#define M_TOTAL 4096
#define K_TOTAL 4096
#define N_TOTAL 16384

#define BM 128
#define BN 256
#define BK 32
#define NKT (K_TOTAL / BK)            // 128 k-iterations

#define LDE 40                        // smem pitch in fp16 elems (80 B)
#define A_TILE_B (BM * LDE * 2)       // 10240
#define B_TILE_B (BN * LDE * 2)       // 20480
#define STAGE_BYTES (A_TILE_B + B_TILE_B)   // 30720
#define STAGES 4
#define SMEM_TOTAL (STAGES * STAGE_BYTES)   // 122880 (epilogue 67584 reuses it)
#define LDC 132                       // epilogue f32 staging pitch (128x132)

// ---------------- scratch: converted operands ----------------
__device__ __half g_xh[(size_t)M_TOTAL * K_TOTAL];   // 32 MB
__device__ __half g_wh[(size_t)N_TOTAL * K_TOTAL];   // 128 MB

// ---------------- helpers ----------------
__device__ __forceinline__ uint32_t smem_u32(const void* p) {
    uint32_t a;
    asm("{ .reg .u64 t; cvta.to.shared.u64 t, %1; cvt.u32.u64 %0, t; }"
        : "=r"(a) : "l"(p));
    return a;
}
__device__ __forceinline__ void cp16(uint32_t dst, const void* src) {
    asm volatile("cp.async.cg.shared.global [%0], [%1], 16;" :: "r"(dst), "l"(src));
}

// ---------------- pre-pass 1: x fp32 -> fp16 ----------------
__global__ void k_conv_x(const float* __restrict__ x) {
    size_t i = ((size_t)blockIdx.x * 256 + threadIdx.x) * 16;
    float f[16];
#pragma unroll
    for (int j = 0; j < 16; j += 4)
        *reinterpret_cast<float4*>(f + j) = *reinterpret_cast<const float4*>(x + i + j);
    __align__(16) __half2 h[8];
#pragma unroll
    for (int j = 0; j < 8; j++) h[j] = __floats2half2_rn(f[2 * j], f[2 * j + 1]);
    *reinterpret_cast<uint4*>(&g_xh[i])     = reinterpret_cast<uint4*>(h)[0];
    *reinterpret_cast<uint4*>(&g_xh[i + 8]) = reinterpret_cast<uint4*>(h)[1];
}

// ---------------- pre-pass 2: W int32 (harness-promoted int8) -> fp16 (exact) ----------------
__global__ void k_conv_w(const int* __restrict__ w) {
    size_t i = ((size_t)blockIdx.x * 256 + threadIdx.x) * 16;
    int v[16];
#pragma unroll
    for (int j = 0; j < 16; j += 4)
        *reinterpret_cast<int4*>(v + j) = *reinterpret_cast<const int4*>(w + i + j);
    __align__(16) __half h[16];
#pragma unroll
    for (int j = 0; j < 16; j++) h[j] = __int2half_rn(v[j]);
    *reinterpret_cast<uint4*>(&g_wh[i])     = reinterpret_cast<uint4*>(h)[0];
    *reinterpret_cast<uint4*>(&g_wh[i + 8]) = reinterpret_cast<uint4*>(h)[1];
}

// ---------------- main GEMM: fp16, 128x256 CTA, 512 threads, 32x64 warp tiles ----------------
__global__ void __launch_bounds__(512, 1) k_gemm(
    const float* __restrict__ sc, const float* __restrict__ bi,
    float* __restrict__ out)
{
    extern __shared__ __align__(16) char smem[];
    const uint32_t sb = smem_u32(smem);
    const int tid = threadIdx.x;
    const int wid = tid >> 5;
    const int m0 = blockIdx.x * BM;     // M fastest -> x tiles L2-resident per wave
    const int n0 = blockIdx.y * BN;

    const int warp_m = (wid & 3) * 32;  // 4 warps along M
    const int warp_n = (wid >> 2) * 64; // 4 warps along N

    // global->smem assignment (512 threads):
    //   A: 128 rows x 4 x 16B slots -> 1 cp16/thread: row = tid/4, seg = tid%4
    //   B: 256 rows x 4 x 16B slots -> 2 cp16/thread: row = tid/2, 32B half = tid%2
    const int arow = tid >> 2, aseg = tid & 3;
    const int brow = tid >> 1, bhalf = tid & 1;
    const char* gA = (const char*)g_xh + (size_t)(m0 + arow) * (K_TOTAL * 2) + aseg * 16;
    const char* gB = (const char*)g_wh + (size_t)(n0 + brow) * (K_TOTAL * 2) + bhalf * 32;
    const uint32_t soA = (uint32_t)arow * 80 + aseg * 16;
    const uint32_t soB = (uint32_t)brow * 80 + bhalf * 32;

    wmma::fragment<wmma::accumulator, 16, 16, 16, float> acc[2][4];
#pragma unroll
    for (int f = 0; f < 2; f++)
#pragma unroll
        for (int g = 0; g < 4; g++) wmma::fill_fragment(acc[f][g], 0.0f);

#define FILL(s, kt) do {                                                    \
        uint32_t st_ = sb + (uint32_t)(s) * STAGE_BYTES;                    \
        size_t   o_  = (size_t)(kt) * 64;                                   \
        cp16(st_ + soA,                 gA + o_);                           \
        cp16(st_ + A_TILE_B + soB,      gB + o_);                           \
        cp16(st_ + A_TILE_B + soB + 16, gB + o_ + 16);                      \
    } while (0)

    // prologue: stages 0..2
#pragma unroll
    for (int p = 0; p < STAGES - 1; p++) {
        FILL(p, p);
        asm volatile("cp.async.commit_group;" ::: "memory");
    }

    for (int kt = 0; kt < NKT; kt++) {
        const int s = kt & (STAGES - 1);

        asm volatile("cp.async.wait_group %0;" :: "n"(STAGES - 2) : "memory");
        __syncthreads();

        if (kt + STAGES - 1 < NKT) {
            FILL((kt + STAGES - 1) & (STAGES - 1), kt + STAGES - 1);
        }
        asm volatile("cp.async.commit_group;" ::: "memory");

        const __half* sA = (const __half*)(smem + (size_t)s * STAGE_BYTES);
        const __half* sB = (const __half*)(smem + (size_t)s * STAGE_BYTES + A_TILE_B);

#pragma unroll
        for (int h = 0; h < 2; h++) {            // two k16 halves of BK=32
            wmma::fragment<wmma::matrix_a, 16, 16, 16, __half, wmma::row_major> af[2];
            wmma::fragment<wmma::matrix_b, 16, 16, 16, __half, wmma::col_major> bf[4];
#pragma unroll
            for (int f = 0; f < 2; f++)
                wmma::load_matrix_sync(af[f], sA + (warp_m + 16 * f) * LDE + h * 16, LDE);
#pragma unroll
            for (int g = 0; g < 4; g++)
                wmma::load_matrix_sync(bf[g], sB + (warp_n + 16 * g) * LDE + h * 16, LDE);
#pragma unroll
            for (int f = 0; f < 2; f++)
#pragma unroll
                for (int g = 0; g < 4; g++)
                    wmma::mma_sync(acc[f][g], af[f], bf[g], acc[f][g]);
        }
    }
#undef FILL

    // ---------------- epilogue: two 128x128 phases through smem ----------------
    float* sf = (float*)smem;                    // 128 x 132 f32 = 67584 B
#pragma unroll 1
    for (int phase = 0; phase < 2; phase++) {
        __syncthreads();                          // stage bufs / prev phase free
        if ((warp_n >> 7) == phase) {
            const int cn = warp_n & 127;
#pragma unroll
            for (int f = 0; f < 2; f++)
#pragma unroll
                for (int g = 0; g < 4; g++)
                    wmma::store_matrix_sync(sf + (size_t)(warp_m + 16 * f) * LDC + cn + 16 * g,
                                            acc[f][g], LDC, wmma::mem_row_major);
        }
        __syncthreads();

        const int nb = n0 + phase * 128;
#pragma unroll 4
        for (int i = 0; i < 8; i++) {             // 128 rows x 32 float4, 512 threads
            const int lin = i * 512 + tid;
            const int rr = lin >> 5;
            const int c4 = (lin & 31) * 4;
            float4 v4 = *reinterpret_cast<const float4*>(sf + (size_t)rr * LDC + c4);
            const float4 s4 = *reinterpret_cast<const float4*>(sc + nb + c4);
            const float4 b4 = *reinterpret_cast<const float4*>(bi + nb + c4);
            v4.x = fmaf(v4.x, s4.x, b4.x);
            v4.y = fmaf(v4.y, s4.y, b4.y);
            v4.z = fmaf(v4.z, s4.z, b4.z);
            v4.w = fmaf(v4.w, s4.w, b4.w);
            *reinterpret_cast<float4*>(out + (size_t)(m0 + rr) * N_TOTAL + nb + c4) = v4;
        }
    }
}

// ---------------- launch ----------------
extern "C" void kernel_launch(void* const* d_in, const int* in_sizes, int n_in,
                              void* d_out, int out_size) {
    // x = 16777216 f32, qw = 67108864 int32 (promoted int8), scale/bias = 16384 each.
    int i_x = -1, big[2] = {-1, -1}, nbig = 0, smalls[2] = {-1, -1}, nsmall = 0;
    for (int i = 0; i < n_in; i++) {
        if (in_sizes[i] == 16777216) i_x = i;
        else if (in_sizes[i] == 67108864) { if (nbig < 2) big[nbig] = i; nbig++; }
        else { if (nsmall < 2) smalls[nsmall] = i; nsmall++; }
    }
    const float* x; const int* qw;
    if (i_x >= 0 && nbig >= 1) { x = (const float*)d_in[i_x]; qw = (const int*)d_in[big[0]]; }
    else if (nbig == 2)        { x = (const float*)d_in[big[0]]; qw = (const int*)d_in[big[1]]; }
    else                       { x = (const float*)d_in[0]; qw = (const int*)d_in[1]; }
    const float* scale = (nsmall >= 1) ? (const float*)d_in[smalls[0]] : (const float*)d_in[2];
    const float* bias  = (nsmall >= 2) ? (const float*)d_in[smalls[1]] : (const float*)d_in[3];
    float* out = (float*)d_out;

    k_conv_x<<<((size_t)M_TOTAL * K_TOTAL) / 16 / 256, 256>>>(x);
    k_conv_w<<<((size_t)N_TOTAL * K_TOTAL) / 16 / 256, 256>>>(qw);

    cudaFuncSetAttribute(k_gemm, cudaFuncAttributeMaxDynamicSharedMemorySize, SMEM_TOTAL);
    dim3 grid(M_TOTAL / BM, N_TOTAL / BN);   // (32, 64), M fastest
    k_gemm<<<grid, 512, SMEM_TOTAL>>>(scale, bias, out);
}

// round 10
// speedup vs baseline: 3.5965x; 1.0917x over previous
#include <cuda_runtime.h>
#include <cuda_fp16.h>
#include <cstdint>

// ---------------- problem sizes ----------------
#define M_TOTAL 4096
#define K_TOTAL 4096
#define N_TOTAL 16384

#define BM 128
#define BN 128
#define BK 32
#define NKT (K_TOTAL / BK)            // 128 k-iterations

#define PITCH 80                      // bytes per smem row (64B data + 16B pad)
#define A_TILE_B (BM * PITCH)         // 10240
#define B_TILE_B (BN * PITCH)         // 10240
#define STAGE_BYTES (A_TILE_B + B_TILE_B)   // 20480
#define STAGES 4
#define SMEM_TOTAL (STAGES * STAGE_BYTES)   // 81920 (>= epilogue 67584)
#define LDC 132                       // epilogue f32 staging pitch

// ---------------- scratch: converted operands ----------------
__device__ __half g_xh[(size_t)M_TOTAL * K_TOTAL];   // 32 MB
__device__ __half g_wh[(size_t)N_TOTAL * K_TOTAL];   // 128 MB

// ---------------- helpers ----------------
__device__ __forceinline__ uint32_t smem_u32(const void* p) {
    uint32_t a;
    asm("{ .reg .u64 t; cvta.to.shared.u64 t, %1; cvt.u32.u64 %0, t; }"
        : "=r"(a) : "l"(p));
    return a;
}
__device__ __forceinline__ void cp16(uint32_t dst, const void* src) {
    asm volatile("cp.async.cg.shared.global [%0], [%1], 16;" :: "r"(dst), "l"(src));
}
__device__ __forceinline__ void ldsm4(uint32_t* r, uint32_t a) {
    asm volatile("ldmatrix.sync.aligned.m8n8.x4.shared.b16 {%0,%1,%2,%3}, [%4];"
                 : "=r"(r[0]), "=r"(r[1]), "=r"(r[2]), "=r"(r[3]) : "r"(a));
}
__device__ __forceinline__ void mma16816(float* c, const uint32_t* a, const uint32_t* b) {
    asm volatile(
        "mma.sync.aligned.m16n8k16.row.col.f32.f16.f16.f32 "
        "{%0,%1,%2,%3}, {%4,%5,%6,%7}, {%8,%9}, {%0,%1,%2,%3};"
        : "+f"(c[0]), "+f"(c[1]), "+f"(c[2]), "+f"(c[3])
        : "r"(a[0]), "r"(a[1]), "r"(a[2]), "r"(a[3]), "r"(b[0]), "r"(b[1]));
}

// ---------------- pre-pass 1: x fp32 -> fp16 ----------------
__global__ void k_conv_x(const float* __restrict__ x) {
    size_t i = ((size_t)blockIdx.x * 256 + threadIdx.x) * 16;
    float f[16];
#pragma unroll
    for (int j = 0; j < 16; j += 4)
        *reinterpret_cast<float4*>(f + j) = *reinterpret_cast<const float4*>(x + i + j);
    __align__(16) __half2 h[8];
#pragma unroll
    for (int j = 0; j < 8; j++) h[j] = __floats2half2_rn(f[2 * j], f[2 * j + 1]);
    *reinterpret_cast<uint4*>(&g_xh[i])     = reinterpret_cast<uint4*>(h)[0];
    *reinterpret_cast<uint4*>(&g_xh[i + 8]) = reinterpret_cast<uint4*>(h)[1];
}

// ---------------- pre-pass 2: W int32 (harness-promoted int8) -> fp16 (exact) ----------------
__global__ void k_conv_w(const int* __restrict__ w) {
    size_t i = ((size_t)blockIdx.x * 256 + threadIdx.x) * 16;
    int v[16];
#pragma unroll
    for (int j = 0; j < 16; j += 4)
        *reinterpret_cast<int4*>(v + j) = *reinterpret_cast<const int4*>(w + i + j);
    __align__(16) __half h[16];
#pragma unroll
    for (int j = 0; j < 16; j++) h[j] = __int2half_rn(v[j]);
    *reinterpret_cast<uint4*>(&g_wh[i])     = reinterpret_cast<uint4*>(h)[0];
    *reinterpret_cast<uint4*>(&g_wh[i + 8]) = reinterpret_cast<uint4*>(h)[1];
}

// ---------------- main GEMM: 128x128 CTA, 256 thr, 2 CTAs/SM, hand mma.sync ----------------
__global__ void __launch_bounds__(256, 2) k_gemm(
    const float* __restrict__ sc, const float* __restrict__ bi,
    float* __restrict__ out)
{
    extern __shared__ __align__(16) char smem[];
    const uint32_t sb = smem_u32(smem);
    const int tid  = threadIdx.x;
    const int wid  = tid >> 5;
    const int lane = tid & 31;
    const int m0 = blockIdx.x * BM;    // M fastest -> x tiles L2-resident per wave
    const int n0 = blockIdx.y * BN;

    const int warp_m = (wid & 3) * 32; // 4 warps along M
    const int warp_n = (wid >> 2) * 64;// 2 warps along N

    // global->smem: row = tid/2, 32B half = tid%2; 2 cp16 per operand per thread
    const int r    = tid >> 1;
    const int half = tid & 1;
    const char* gA = (const char*)g_xh + (size_t)(m0 + r) * (K_TOTAL * 2) + half * 32;
    const char* gB = (const char*)g_wh + (size_t)(n0 + r) * (K_TOTAL * 2) + half * 32;
    const uint32_t so = (uint32_t)r * PITCH + half * 32;

    // ldmatrix lane offsets (validated fragment math)
    const uint32_t aoff = (uint32_t)(lane & 15) * PITCH + (lane >> 4) * 16;
    const uint32_t boff = (uint32_t)((lane & 7) + ((lane >> 4) << 3)) * PITCH
                        + ((lane >> 3) & 1) * 16;

    float acc[2][8][4];
#pragma unroll
    for (int f = 0; f < 2; f++)
#pragma unroll
        for (int j = 0; j < 8; j++)
#pragma unroll
            for (int c = 0; c < 4; c++) acc[f][j][c] = 0.0f;

#define FILL(s, kt) do {                                                  \
        uint32_t b_ = sb + (uint32_t)(s) * STAGE_BYTES + so;              \
        size_t   o_ = (size_t)(kt) * 64;                                  \
        cp16(b_,                gA + o_);                                 \
        cp16(b_ + 16,           gA + o_ + 16);                            \
        cp16(b_ + A_TILE_B,      gB + o_);                                \
        cp16(b_ + A_TILE_B + 16, gB + o_ + 16);                           \
    } while (0)

    // prologue: stages 0..2
#pragma unroll
    for (int p = 0; p < STAGES - 1; p++) {
        FILL(p, p);
        asm volatile("cp.async.commit_group;" ::: "memory");
    }

    for (int kt = 0; kt < NKT; kt++) {
        const int s = kt & (STAGES - 1);

        asm volatile("cp.async.wait_group %0;" :: "n"(STAGES - 2) : "memory");
        __syncthreads();

        if (kt + STAGES - 1 < NKT) {
            FILL((kt + STAGES - 1) & (STAGES - 1), kt + STAGES - 1);
        }
        asm volatile("cp.async.commit_group;" ::: "memory");

        const uint32_t stA = sb + (uint32_t)s * STAGE_BYTES;
        const uint32_t stB = stA + A_TILE_B;

#pragma unroll
        for (int h = 0; h < 2; h++) {              // two k16 halves of BK=32
            uint32_t af[2][4], bq[4][4];
#pragma unroll
            for (int f = 0; f < 2; f++)
                ldsm4(af[f], stA + (uint32_t)(warp_m + 16 * f) * PITCH + aoff + h * 32);
#pragma unroll
            for (int g = 0; g < 4; g++)
                ldsm4(bq[g], stB + (uint32_t)(warp_n + 16 * g) * PITCH + boff + h * 32);
#pragma unroll
            for (int f = 0; f < 2; f++)
#pragma unroll
                for (int j = 0; j < 8; j++)
                    mma16816(acc[f][j], af[f], &bq[j >> 1][(j & 1) * 2]);
        }
    }
#undef FILL

    // ---------------- epilogue: smem staging, fused scale/bias, float4 stores ----------------
    __syncthreads();                                // stage buffers free
    float* sf = (float*)smem;                       // 128 x 132 f32 = 67584 B
    {
        const int qr = lane >> 2;                   // row within 8
        const int qc = (lane & 3) * 2;              // col pair
#pragma unroll
        for (int f = 0; f < 2; f++)
#pragma unroll
            for (int j = 0; j < 8; j++) {
                float* p0 = sf + (size_t)(warp_m + 16 * f + qr) * LDC + warp_n + 8 * j + qc;
                p0[0] = acc[f][j][0];
                p0[1] = acc[f][j][1];
                float* p1 = p0 + 8 * LDC;
                p1[0] = acc[f][j][2];
                p1[1] = acc[f][j][3];
            }
    }
    __syncthreads();

#pragma unroll 4
    for (int i = 0; i < 16; i++) {                  // 128 rows x 32 float4, 256 threads
        const int lin = i * 256 + tid;
        const int rr = lin >> 5;
        const int c4 = (lin & 31) * 4;
        float4 v4 = *reinterpret_cast<const float4*>(sf + (size_t)rr * LDC + c4);
        const float4 s4 = *reinterpret_cast<const float4*>(sc + n0 + c4);
        const float4 b4 = *reinterpret_cast<const float4*>(bi + n0 + c4);
        v4.x = fmaf(v4.x, s4.x, b4.x);
        v4.y = fmaf(v4.y, s4.y, b4.y);
        v4.z = fmaf(v4.z, s4.z, b4.z);
        v4.w = fmaf(v4.w, s4.w, b4.w);
        *reinterpret_cast<float4*>(out + (size_t)(m0 + rr) * N_TOTAL + n0 + c4) = v4;
    }
}

// ---------------- launch ----------------
extern "C" void kernel_launch(void* const* d_in, const int* in_sizes, int n_in,
                              void* d_out, int out_size) {
    // x = 16777216 f32, qw = 67108864 int32 (promoted int8), scale/bias = 16384 each.
    int i_x = -1, big[2] = {-1, -1}, nbig = 0, smalls[2] = {-1, -1}, nsmall = 0;
    for (int i = 0; i < n_in; i++) {
        if (in_sizes[i] == 16777216) i_x = i;
        else if (in_sizes[i] == 67108864) { if (nbig < 2) big[nbig] = i; nbig++; }
        else { if (nsmall < 2) smalls[nsmall] = i; nsmall++; }
    }
    const float* x; const int* qw;
    if (i_x >= 0 && nbig >= 1) { x = (const float*)d_in[i_x]; qw = (const int*)d_in[big[0]]; }
    else if (nbig == 2)        { x = (const float*)d_in[big[0]]; qw = (const int*)d_in[big[1]]; }
    else                       { x = (const float*)d_in[0]; qw = (const int*)d_in[1]; }
    const float* scale = (nsmall >= 1) ? (const float*)d_in[smalls[0]] : (const float*)d_in[2];
    const float* bias  = (nsmall >= 2) ? (const float*)d_in[smalls[1]] : (const float*)d_in[3];
    float* out = (float*)d_out;

    k_conv_x<<<((size_t)M_TOTAL * K_TOTAL) / 16 / 256, 256>>>(x);
    k_conv_w<<<((size_t)N_TOTAL * K_TOTAL) / 16 / 256, 256>>>(qw);

    cudaFuncSetAttribute(k_gemm, cudaFuncAttributeMaxDynamicSharedMemorySize, SMEM_TOTAL);
    dim3 grid(M_TOTAL / BM, N_TOTAL / BN);   // (32, 128), M fastest
    k_gemm<<<grid, 256, SMEM_TOTAL>>>(scale, bias, out);
}